// round 2
// baseline (speedup 1.0000x reference)
#include <cuda_runtime.h>
#include <math.h>

#define NN 20000
#define NE 320000
#define NET (NE + NN)   // 340000 with self loops

// ---------------- scratch (static device globals; no allocations) ----------
__device__ float g_h0[NN * 32];      // text projection output
__device__ float g_hA[NN * 256];     // layer buffer A
__device__ float g_hB[NN * 256];     // layer buffer B
__device__ float g_xl[NN * 256];     // xl projection
__device__ float g_xr[NN * 256];     // xr projection
__device__ float g_h4[NN * 32];      // final node features
__device__ float g_logit[NET * 8];   // per-edge per-head logits
__device__ int   g_indptr[NN + 1];
__device__ int   g_fill[NN];
__device__ int   g_col[NET];         // src node per CSR slot (sorted by dst)

// ---------------- CSR build ------------------------------------------------
__global__ void k_init_counts() {
    int i = blockIdx.x * blockDim.x + threadIdx.x;
    if (i < NN) g_fill[i] = 1;  // self loop
}

__global__ void k_hist(const int* __restrict__ ei) {
    int e = blockIdx.x * blockDim.x + threadIdx.x;
    if (e < NE) atomicAdd(&g_fill[ei[NE + e]], 1);
}

// single-block chunked Hillis-Steele exclusive scan of g_fill -> g_indptr
__global__ void k_scan() {
    __shared__ int sh[1024];
    __shared__ int carry;
    int tid = threadIdx.x;
    if (tid == 0) carry = 0;
    __syncthreads();
    for (int base = 0; base < NN; base += 1024) {
        int i = base + tid;
        int v = (i < NN) ? g_fill[i] : 0;
        sh[tid] = v;
        __syncthreads();
        for (int off = 1; off < 1024; off <<= 1) {
            int t = (tid >= off) ? sh[tid - off] : 0;
            __syncthreads();
            sh[tid] += t;
            __syncthreads();
        }
        if (i < NN) g_indptr[i] = carry + sh[tid] - v;
        __syncthreads();
        if (tid == 1023) carry += sh[1023];
        __syncthreads();
    }
    if (tid == 0) g_indptr[NN] = carry;
}

__global__ void k_cursor() {
    int i = blockIdx.x * blockDim.x + threadIdx.x;
    if (i < NN) g_fill[i] = g_indptr[i];
}

__global__ void k_scatter(const int* __restrict__ ei) {
    int t = blockIdx.x * blockDim.x + threadIdx.x;
    if (t < NE) {
        int s = ei[t], d = ei[NE + t];
        int pos = atomicAdd(&g_fill[d], 1);
        g_col[pos] = s;
    } else if (t < NET) {
        int i = t - NE;
        int pos = atomicAdd(&g_fill[i], 1);
        g_col[pos] = i;
    }
}

// ---------------- GEMM: C[n,m] = A[n,K] @ W[m,K]^T (+ bias) ----------------
// 256 threads, tile BN x BM, micro-tile TN x TM per thread, BK=16.
template <int BN, int BM, int TN, int TM>
__global__ __launch_bounds__(256) void gemm_tn(
    const float* __restrict__ A, const float* __restrict__ W,
    const float* __restrict__ bias, float* __restrict__ C,
    int n, int m, int K)
{
    constexpr int BK = 16;
    constexpr int CT = BM / TM;   // threads across columns
    constexpr int RT = BN / TN;   // threads across rows
    static_assert(CT * RT == 256, "bad tile");
    __shared__ float As[BK][BN + 4];
    __shared__ float Ws[BK][BM + 4];

    const int tid = threadIdx.x;
    const int tx = tid % CT;
    const int ty = tid / CT;

    float acc[TN][TM];
#pragma unroll
    for (int i = 0; i < TN; i++)
#pragma unroll
        for (int j = 0; j < TM; j++) acc[i][j] = 0.f;

    for (int k0 = 0; k0 < K; k0 += BK) {
        for (int idx = tid * 4; idx < BN * BK; idx += 256 * 4) {
            int r = idx / BK, kq = idx % BK;
            int row = blockIdx.x * BN + r;
            float4 v = make_float4(0.f, 0.f, 0.f, 0.f);
            if (row < n) v = *(const float4*)&A[(size_t)row * K + k0 + kq];
            As[kq + 0][r] = v.x; As[kq + 1][r] = v.y;
            As[kq + 2][r] = v.z; As[kq + 3][r] = v.w;
        }
        for (int idx = tid * 4; idx < BM * BK; idx += 256 * 4) {
            int r = idx / BK, kq = idx % BK;
            int row = blockIdx.y * BM + r;
            float4 v = make_float4(0.f, 0.f, 0.f, 0.f);
            if (row < m) v = *(const float4*)&W[(size_t)row * K + k0 + kq];
            Ws[kq + 0][r] = v.x; Ws[kq + 1][r] = v.y;
            Ws[kq + 2][r] = v.z; Ws[kq + 3][r] = v.w;
        }
        __syncthreads();
#pragma unroll
        for (int k = 0; k < BK; k++) {
            float ar[TN], br[TM];
#pragma unroll
            for (int i = 0; i < TN; i++) ar[i] = As[k][ty + i * RT];
#pragma unroll
            for (int j = 0; j < TM; j++) br[j] = Ws[k][tx + j * CT];
#pragma unroll
            for (int i = 0; i < TN; i++)
#pragma unroll
                for (int j = 0; j < TM; j++)
                    acc[i][j] = fmaf(ar[i], br[j], acc[i][j]);
        }
        __syncthreads();
    }
#pragma unroll
    for (int i = 0; i < TN; i++) {
        int row = blockIdx.x * BN + ty + i * RT;
        if (row >= n) continue;
#pragma unroll
        for (int j = 0; j < TM; j++) {
            int col = blockIdx.y * BM + tx + j * CT;
            if (col < m)
                C[(size_t)row * m + col] = acc[i][j] + (bias ? bias[col] : 0.f);
        }
    }
}

// ---------------- fused GATv2 layer: warp per node -------------------------
// pass 1: logits + per-head max (store logits)
// pass 2: accumulate unnormalized sum(p * xl[src]) and denom = sum(p), then
//         scale by 1/denom; + bias + optional residual + layernorm + ELU
template <int HEADS, int CDIM, bool ELU>
__global__ __launch_bounds__(256) void gat_kernel(
    const float* __restrict__ att, const float* __restrict__ bias,
    const float* __restrict__ resid,
    const float* __restrict__ lnw, const float* __restrict__ lnb,
    float* __restrict__ out)
{
    constexpr int HC_ = HEADS * CDIM;
    constexpr int VPL = HC_ / 32;     // values per lane
    constexpr int LPH = 32 / HEADS;   // lanes per head

    int gw = (blockIdx.x * blockDim.x + threadIdx.x) >> 5;
    if (gw >= NN) return;
    int lane = threadIdx.x & 31;
    const int beg = g_indptr[gw], end = g_indptr[gw + 1];
    const int hofs = lane / LPH;

    float xrv[VPL], attv[VPL];
    {
        const float* xrp = g_xr + (size_t)gw * HC_ + lane * VPL;
        const float* atp = att + lane * VPL;
        if constexpr (VPL % 4 == 0) {
#pragma unroll
            for (int q = 0; q < VPL / 4; q++) {
                float4 a = ((const float4*)xrp)[q];
                xrv[4 * q] = a.x; xrv[4 * q + 1] = a.y; xrv[4 * q + 2] = a.z; xrv[4 * q + 3] = a.w;
                float4 b = ((const float4*)atp)[q];
                attv[4 * q] = b.x; attv[4 * q + 1] = b.y; attv[4 * q + 2] = b.z; attv[4 * q + 3] = b.w;
            }
        } else {
#pragma unroll
            for (int j = 0; j < VPL; j++) { xrv[j] = xrp[j]; attv[j] = atp[j]; }
        }
    }

    // pass 1: logits + per-head max
    float mx = -INFINITY;
    for (int p = beg; p < end; ++p) {
        int s = g_col[p];
        const float* xls = g_xl + (size_t)s * HC_ + lane * VPL;
        float lg = 0.f;
        if constexpr (VPL % 4 == 0) {
#pragma unroll
            for (int q = 0; q < VPL / 4; q++) {
                float4 a = ((const float4*)xls)[q];
                float v0 = a.x + xrv[4 * q];     v0 = v0 > 0.f ? v0 : 0.2f * v0;
                float v1 = a.y + xrv[4 * q + 1]; v1 = v1 > 0.f ? v1 : 0.2f * v1;
                float v2 = a.z + xrv[4 * q + 2]; v2 = v2 > 0.f ? v2 : 0.2f * v2;
                float v3 = a.w + xrv[4 * q + 3]; v3 = v3 > 0.f ? v3 : 0.2f * v3;
                lg = fmaf(v0, attv[4 * q], lg);
                lg = fmaf(v1, attv[4 * q + 1], lg);
                lg = fmaf(v2, attv[4 * q + 2], lg);
                lg = fmaf(v3, attv[4 * q + 3], lg);
            }
        } else {
#pragma unroll
            for (int j = 0; j < VPL; j++) {
                float v = xls[j] + xrv[j];
                v = v > 0.f ? v : 0.2f * v;
                lg = fmaf(v, attv[j], lg);
            }
        }
#pragma unroll
        for (int off = LPH >> 1; off >= 1; off >>= 1)
            lg += __shfl_xor_sync(0xffffffffu, lg, off);
        mx = fmaxf(mx, lg);
        if ((lane & (LPH - 1)) == 0) g_logit[(size_t)p * HEADS + hofs] = lg;
    }

    // pass 2 (merged denom + aggregation): acc = sum(p * xl), denom = sum(p)
    float acc[VPL];
#pragma unroll
    for (int j = 0; j < VPL; j++) acc[j] = 0.f;
    float denom = 0.f;
    for (int p = beg; p < end; ++p) {
        int s = g_col[p];
        float pe = expf(g_logit[(size_t)p * HEADS + hofs] - mx);
        denom += pe;
        const float* xls = g_xl + (size_t)s * HC_ + lane * VPL;
        if constexpr (VPL % 4 == 0) {
#pragma unroll
            for (int q = 0; q < VPL / 4; q++) {
                float4 a = ((const float4*)xls)[q];
                acc[4 * q]     = fmaf(pe, a.x, acc[4 * q]);
                acc[4 * q + 1] = fmaf(pe, a.y, acc[4 * q + 1]);
                acc[4 * q + 2] = fmaf(pe, a.z, acc[4 * q + 2]);
                acc[4 * q + 3] = fmaf(pe, a.w, acc[4 * q + 3]);
            }
        } else {
#pragma unroll
            for (int j = 0; j < VPL; j++) acc[j] = fmaf(pe, xls[j], acc[j]);
        }
    }
    const float inv = 1.f / (denom + 1e-16f);

    // normalize + bias + residual
#pragma unroll
    for (int j = 0; j < VPL; j++) {
        float o = acc[j] * inv + bias[lane * VPL + j];
        if (resid) o += resid[(size_t)gw * HC_ + lane * VPL + j];
        acc[j] = o;
    }

    // layernorm across the warp's HC_ values
    float s1 = 0.f;
#pragma unroll
    for (int j = 0; j < VPL; j++) s1 += acc[j];
#pragma unroll
    for (int off = 16; off >= 1; off >>= 1) s1 += __shfl_xor_sync(0xffffffffu, s1, off);
    const float mu = s1 * (1.f / HC_);
    float s2 = 0.f;
#pragma unroll
    for (int j = 0; j < VPL; j++) { float d = acc[j] - mu; s2 = fmaf(d, d, s2); }
#pragma unroll
    for (int off = 16; off >= 1; off >>= 1) s2 += __shfl_xor_sync(0xffffffffu, s2, off);
    const float rstd = rsqrtf(s2 * (1.f / HC_) + 1e-5f);

#pragma unroll
    for (int j = 0; j < VPL; j++) {
        int idx = lane * VPL + j;
        float y = (acc[j] - mu) * rstd * lnw[idx] + lnb[idx];
        if constexpr (ELU) y = y > 0.f ? y : expm1f(y);
        out[(size_t)gw * HC_ + idx] = y;
    }
}

// ---------------- readout --------------------------------------------------
__global__ void k_final(const int* __restrict__ ptr,
                        const float* __restrict__ lin_w,
                        const float* __restrict__ lin_b,
                        float* __restrict__ out)
{
    int g = threadIdx.x >> 5;
    int lane = threadIdx.x & 31;
    if (g < 8) {
        int nid = ptr[g];
        float v = g_h4[(size_t)nid * 32 + lane] * lin_w[lane];
#pragma unroll
        for (int off = 16; off >= 1; off >>= 1) v += __shfl_xor_sync(0xffffffffu, v, off);
        if (lane == 0) out[g] = v + lin_b[0];
    }
}

// ---------------- host -----------------------------------------------------
extern "C" void kernel_launch(void* const* d_in, const int* in_sizes, int n_in,
                              void* d_out, int out_size)
{
    const float* x     = (const float*)d_in[0];
    const int*   ei    = (const int*)d_in[1];
    const int*   ptr   = (const int*)d_in[2];
    const float* tp_w  = (const float*)d_in[3];
    const float* tp_b  = (const float*)d_in[4];
    const float* wl1   = (const float*)d_in[5];
    const float* wr1   = (const float*)d_in[6];
    const float* att1  = (const float*)d_in[7];
    const float* b1    = (const float*)d_in[8];
    const float* wl2   = (const float*)d_in[9];
    const float* wr2   = (const float*)d_in[10];
    const float* att2  = (const float*)d_in[11];
    const float* b2    = (const float*)d_in[12];
    const float* wl3   = (const float*)d_in[13];
    const float* wr3   = (const float*)d_in[14];
    const float* att3  = (const float*)d_in[15];
    const float* b3    = (const float*)d_in[16];
    const float* wl4   = (const float*)d_in[17];
    const float* wr4   = (const float*)d_in[18];
    const float* att4  = (const float*)d_in[19];
    const float* b4    = (const float*)d_in[20];
    const float* n1w   = (const float*)d_in[21];
    const float* n1b   = (const float*)d_in[22];
    const float* n2w   = (const float*)d_in[23];
    const float* n2b   = (const float*)d_in[24];
    const float* n3w   = (const float*)d_in[25];
    const float* n3b   = (const float*)d_in[26];
    const float* n4w   = (const float*)d_in[27];
    const float* n4b   = (const float*)d_in[28];
    const float* lin_w = (const float*)d_in[29];
    const float* lin_b = (const float*)d_in[30];

    float *h0, *hA, *hB, *xl, *xr, *h4;
    cudaGetSymbolAddress((void**)&h0, g_h0);
    cudaGetSymbolAddress((void**)&hA, g_hA);
    cudaGetSymbolAddress((void**)&hB, g_hB);
    cudaGetSymbolAddress((void**)&xl, g_xl);
    cudaGetSymbolAddress((void**)&xr, g_xr);
    cudaGetSymbolAddress((void**)&h4, g_h4);

    // CSR by dst
    k_init_counts<<<(NN + 255) / 256, 256>>>();
    k_hist<<<(NE + 255) / 256, 256>>>(ei);
    k_scan<<<1, 1024>>>();
    k_cursor<<<(NN + 255) / 256, 256>>>();
    k_scatter<<<(NET + 255) / 256, 256>>>(ei);

    const dim3 gBig((NN + 127) / 128, (256 + 127) / 128);  // 157 x 2
    const dim3 gSm((NN + 63) / 64, 1);                      // 313 x 1
    const int gatGrid = (NN + 7) / 8;                       // 2500

    // text projection: h0 = x @ tp_w^T + tp_b  (K=768, M=32)
    gemm_tn<64, 32, 4, 2><<<gSm, 256>>>(x, tp_w, tp_b, h0, NN, 32, 768);

    // layer 1 (K=32, M=256)
    gemm_tn<128, 128, 8, 8><<<gBig, 256>>>(h0, wl1, nullptr, xl, NN, 256, 32);
    gemm_tn<128, 128, 8, 8><<<gBig, 256>>>(h0, wr1, nullptr, xr, NN, 256, 32);
    gat_kernel<8, 32, true><<<gatGrid, 256>>>(att1, b1, nullptr, n1w, n1b, hA);

    // layer 2 (K=256, M=256), residual hA
    gemm_tn<128, 128, 8, 8><<<gBig, 256>>>(hA, wl2, nullptr, xl, NN, 256, 256);
    gemm_tn<128, 128, 8, 8><<<gBig, 256>>>(hA, wr2, nullptr, xr, NN, 256, 256);
    gat_kernel<8, 32, true><<<gatGrid, 256>>>(att2, b2, hA, n2w, n2b, hB);

    // layer 3, residual hB
    gemm_tn<128, 128, 8, 8><<<gBig, 256>>>(hB, wl3, nullptr, xl, NN, 256, 256);
    gemm_tn<128, 128, 8, 8><<<gBig, 256>>>(hB, wr3, nullptr, xr, NN, 256, 256);
    gat_kernel<8, 32, true><<<gatGrid, 256>>>(att3, b3, hB, n3w, n3b, hA);

    // layer 4 (K=256, M=32, 1 head), no residual, no ELU
    gemm_tn<64, 32, 4, 2><<<gSm, 256>>>(hA, wl4, nullptr, xl, NN, 32, 256);
    gemm_tn<64, 32, 4, 2><<<gSm, 256>>>(hA, wr4, nullptr, xr, NN, 32, 256);
    gat_kernel<1, 32, false><<<gatGrid, 256>>>(att4, b4, nullptr, n4w, n4b, h4);

    // readout
    k_final<<<1, 256>>>(ptr, lin_w, lin_b, (float*)d_out);
}

// round 3
// speedup vs baseline: 1.2377x; 1.2377x over previous
#include <cuda_runtime.h>
#include <math.h>

#define NN 20000
#define NE 320000
#define NET (NE + NN)   // 340000 with self loops

// ---------------- scratch (static device globals; no allocations) ----------
__device__ float g_h0[NN * 32];      // text projection output
__device__ float g_hA[NN * 256];     // layer buffer A
__device__ float g_hB[NN * 256];     // layer buffer B
__device__ float g_xl[NN * 256];     // xl projection
__device__ float g_xr[NN * 256];     // xr projection
__device__ float g_h4[NN * 32];      // final node features
__device__ int   g_indptr[NN + 1];
__device__ int   g_fill[NN];
__device__ int   g_col[NET];         // src node per CSR slot (sorted by dst)

// ---------------- CSR build ------------------------------------------------
__global__ void k_init_counts() {
    int i = blockIdx.x * blockDim.x + threadIdx.x;
    if (i < NN) g_fill[i] = 1;  // self loop
}

__global__ void k_hist(const int* __restrict__ ei) {
    int e = blockIdx.x * blockDim.x + threadIdx.x;
    if (e < NE) atomicAdd(&g_fill[ei[NE + e]], 1);
}

// single-block chunked Hillis-Steele exclusive scan of g_fill -> g_indptr
__global__ void k_scan() {
    __shared__ int sh[1024];
    __shared__ int carry;
    int tid = threadIdx.x;
    if (tid == 0) carry = 0;
    __syncthreads();
    for (int base = 0; base < NN; base += 1024) {
        int i = base + tid;
        int v = (i < NN) ? g_fill[i] : 0;
        sh[tid] = v;
        __syncthreads();
        for (int off = 1; off < 1024; off <<= 1) {
            int t = (tid >= off) ? sh[tid - off] : 0;
            __syncthreads();
            sh[tid] += t;
            __syncthreads();
        }
        if (i < NN) g_indptr[i] = carry + sh[tid] - v;
        __syncthreads();
        if (tid == 1023) carry += sh[1023];
        __syncthreads();
    }
    if (tid == 0) g_indptr[NN] = carry;
}

__global__ void k_cursor() {
    int i = blockIdx.x * blockDim.x + threadIdx.x;
    if (i < NN) g_fill[i] = g_indptr[i];
}

__global__ void k_scatter(const int* __restrict__ ei) {
    int t = blockIdx.x * blockDim.x + threadIdx.x;
    if (t < NE) {
        int s = ei[t], d = ei[NE + t];
        int pos = atomicAdd(&g_fill[d], 1);
        g_col[pos] = s;
    } else if (t < NET) {
        int i = t - NE;
        int pos = atomicAdd(&g_fill[i], 1);
        g_col[pos] = i;
    }
}

// ---------------- GEMM: C[n,m] = A[n,K] @ W[m,K]^T (+ bias) ----------------
// 256 threads, tile BN x BM, micro-tile TN x TM per thread, BK=16.
// Register-prefetch software pipeline: next K-tile is loaded into registers
// while the current smem tile is consumed.
template <int BN, int BM, int TN, int TM>
__global__ __launch_bounds__(256) void gemm_tn(
    const float* __restrict__ A, const float* __restrict__ W,
    const float* __restrict__ bias, float* __restrict__ C,
    int n, int m, int K)
{
    constexpr int BK = 16;
    constexpr int CT = BM / TM;   // threads across columns
    constexpr int RT = BN / TN;   // threads across rows
    static_assert(CT * RT == 256, "bad tile");
    constexpr int LA = (BN * BK + 1023) / 1024;  // float4 loads per thread (A)
    constexpr int LW = (BM * BK + 1023) / 1024;  // float4 loads per thread (W)
    __shared__ float As[BK][BN + 4];
    __shared__ float Ws[BK][BM + 4];

    const int tid = threadIdx.x;
    const int tx = tid % CT;
    const int ty = tid / CT;

    float acc[TN][TM];
#pragma unroll
    for (int i = 0; i < TN; i++)
#pragma unroll
        for (int j = 0; j < TM; j++) acc[i][j] = 0.f;

    float4 rA[LA], rW[LW];

    auto fetch = [&](int k0) {
#pragma unroll
        for (int li = 0; li < LA; li++) {
            int idx = tid * 4 + li * 1024;
            if (idx < BN * BK) {
                int r = idx >> 4, kq = idx & 15;
                int row = blockIdx.x * BN + r;
                rA[li] = (row < n) ? *(const float4*)&A[(size_t)row * K + k0 + kq]
                                   : make_float4(0.f, 0.f, 0.f, 0.f);
            }
        }
#pragma unroll
        for (int li = 0; li < LW; li++) {
            int idx = tid * 4 + li * 1024;
            if (idx < BM * BK) {
                int r = idx >> 4, kq = idx & 15;
                int row = blockIdx.y * BM + r;
                rW[li] = (row < m) ? *(const float4*)&W[(size_t)row * K + k0 + kq]
                                   : make_float4(0.f, 0.f, 0.f, 0.f);
            }
        }
    };
    auto stash = [&]() {
#pragma unroll
        for (int li = 0; li < LA; li++) {
            int idx = tid * 4 + li * 1024;
            if (idx < BN * BK) {
                int r = idx >> 4, kq = idx & 15;
                As[kq + 0][r] = rA[li].x; As[kq + 1][r] = rA[li].y;
                As[kq + 2][r] = rA[li].z; As[kq + 3][r] = rA[li].w;
            }
        }
#pragma unroll
        for (int li = 0; li < LW; li++) {
            int idx = tid * 4 + li * 1024;
            if (idx < BM * BK) {
                int r = idx >> 4, kq = idx & 15;
                Ws[kq + 0][r] = rW[li].x; Ws[kq + 1][r] = rW[li].y;
                Ws[kq + 2][r] = rW[li].z; Ws[kq + 3][r] = rW[li].w;
            }
        }
    };

    const int NT = K / BK;
    fetch(0);
    stash();
    __syncthreads();

    for (int t = 0; t < NT; t++) {
        if (t + 1 < NT) fetch((t + 1) * BK);   // global loads in flight
#pragma unroll
        for (int k = 0; k < BK; k++) {
            float ar[TN], br[TM];
#pragma unroll
            for (int i = 0; i < TN; i++) ar[i] = As[k][ty + i * RT];
#pragma unroll
            for (int j = 0; j < TM; j++) br[j] = Ws[k][tx + j * CT];
#pragma unroll
            for (int i = 0; i < TN; i++)
#pragma unroll
                for (int j = 0; j < TM; j++)
                    acc[i][j] = fmaf(ar[i], br[j], acc[i][j]);
        }
        __syncthreads();
        if (t + 1 < NT) {
            stash();
            __syncthreads();
        }
    }

#pragma unroll
    for (int i = 0; i < TN; i++) {
        int row = blockIdx.x * BN + ty + i * RT;
        if (row >= n) continue;
#pragma unroll
        for (int j = 0; j < TM; j++) {
            int col = blockIdx.y * BM + tx + j * CT;
            if (col < m)
                C[(size_t)row * m + col] = acc[i][j] + (bias ? bias[col] : 0.f);
        }
    }
}

// ---------------- fused GATv2 layer: warp per node, ONE pass over edges ----
// Online softmax: running per-head max m, denom, and accumulator; rescale on
// max update. Each xl[src] row is gathered exactly once.
// Then bias + optional residual + layernorm + optional ELU.
template <int HEADS, int CDIM, bool ELU>
__global__ __launch_bounds__(256) void gat_kernel(
    const float* __restrict__ att, const float* __restrict__ bias,
    const float* __restrict__ resid,
    const float* __restrict__ lnw, const float* __restrict__ lnb,
    float* __restrict__ out)
{
    constexpr int HC_ = HEADS * CDIM;
    constexpr int VPL = HC_ / 32;     // values per lane
    constexpr int LPH = 32 / HEADS;   // lanes per head

    int gw = (blockIdx.x * blockDim.x + threadIdx.x) >> 5;
    if (gw >= NN) return;
    int lane = threadIdx.x & 31;
    const int beg = g_indptr[gw], end = g_indptr[gw + 1];

    float xrv[VPL], attv[VPL];
    {
        const float* xrp = g_xr + (size_t)gw * HC_ + lane * VPL;
        const float* atp = att + lane * VPL;
#pragma unroll
        for (int j = 0; j < VPL; j++) { xrv[j] = xrp[j]; attv[j] = atp[j]; }
    }

    float m = -INFINITY, denom = 0.f;
    float acc[VPL];
#pragma unroll
    for (int j = 0; j < VPL; j++) acc[j] = 0.f;

    // process one already-loaded edge row
    auto process = [&](const float x[VPL]) {
        float lg = 0.f;
#pragma unroll
        for (int j = 0; j < VPL; j++) {
            float v = x[j] + xrv[j];
            v = v > 0.f ? v : 0.2f * v;
            lg = fmaf(v, attv[j], lg);
        }
#pragma unroll
        for (int off = LPH >> 1; off >= 1; off >>= 1)
            lg += __shfl_xor_sync(0xffffffffu, lg, off);
        float mnew = fmaxf(m, lg);
        float sc = expf(m - mnew);     // 0 on first edge (m = -inf)
        float pe = expf(lg - mnew);
        denom = fmaf(denom, sc, pe);
#pragma unroll
        for (int j = 0; j < VPL; j++)
            acc[j] = fmaf(acc[j], sc, pe * x[j]);
        m = mnew;
    };

    auto loadrow = [&](int s, float x[VPL]) {
        const float* xls = g_xl + (size_t)s * HC_ + lane * VPL;
        if constexpr (VPL % 4 == 0) {
#pragma unroll
            for (int q = 0; q < VPL / 4; q++) {
                float4 a = ((const float4*)xls)[q];
                x[4 * q] = a.x; x[4 * q + 1] = a.y;
                x[4 * q + 2] = a.z; x[4 * q + 3] = a.w;
            }
        } else {
#pragma unroll
            for (int j = 0; j < VPL; j++) x[j] = xls[j];
        }
    };

    int p = beg;
    for (; p + 1 < end; p += 2) {   // 2-edge unroll for MLP on the gathers
        int s0 = g_col[p], s1 = g_col[p + 1];
        float x0[VPL], x1[VPL];
        loadrow(s0, x0);
        loadrow(s1, x1);
        process(x0);
        process(x1);
    }
    if (p < end) {
        float x0[VPL];
        loadrow(g_col[p], x0);
        process(x0);
    }

    const float inv = 1.f / (denom + 1e-16f);

    // normalize + bias + residual
#pragma unroll
    for (int j = 0; j < VPL; j++) {
        float o = acc[j] * inv + bias[lane * VPL + j];
        if (resid) o += resid[(size_t)gw * HC_ + lane * VPL + j];
        acc[j] = o;
    }

    // layernorm across the warp's HC_ values
    float s1 = 0.f;
#pragma unroll
    for (int j = 0; j < VPL; j++) s1 += acc[j];
#pragma unroll
    for (int off = 16; off >= 1; off >>= 1) s1 += __shfl_xor_sync(0xffffffffu, s1, off);
    const float mu = s1 * (1.f / HC_);
    float s2 = 0.f;
#pragma unroll
    for (int j = 0; j < VPL; j++) { float d = acc[j] - mu; s2 = fmaf(d, d, s2); }
#pragma unroll
    for (int off = 16; off >= 1; off >>= 1) s2 += __shfl_xor_sync(0xffffffffu, s2, off);
    const float rstd = rsqrtf(s2 * (1.f / HC_) + 1e-5f);

#pragma unroll
    for (int j = 0; j < VPL; j++) {
        int idx = lane * VPL + j;
        float y = (acc[j] - mu) * rstd * lnw[idx] + lnb[idx];
        if constexpr (ELU) y = y > 0.f ? y : expm1f(y);
        out[(size_t)gw * HC_ + idx] = y;
    }
}

// ---------------- readout --------------------------------------------------
__global__ void k_final(const int* __restrict__ ptr,
                        const float* __restrict__ lin_w,
                        const float* __restrict__ lin_b,
                        float* __restrict__ out)
{
    int g = threadIdx.x >> 5;
    int lane = threadIdx.x & 31;
    if (g < 8) {
        int nid = ptr[g];
        float v = g_h4[(size_t)nid * 32 + lane] * lin_w[lane];
#pragma unroll
        for (int off = 16; off >= 1; off >>= 1) v += __shfl_xor_sync(0xffffffffu, v, off);
        if (lane == 0) out[g] = v + lin_b[0];
    }
}

// ---------------- host -----------------------------------------------------
extern "C" void kernel_launch(void* const* d_in, const int* in_sizes, int n_in,
                              void* d_out, int out_size)
{
    const float* x     = (const float*)d_in[0];
    const int*   ei    = (const int*)d_in[1];
    const int*   ptr   = (const int*)d_in[2];
    const float* tp_w  = (const float*)d_in[3];
    const float* tp_b  = (const float*)d_in[4];
    const float* wl1   = (const float*)d_in[5];
    const float* wr1   = (const float*)d_in[6];
    const float* att1  = (const float*)d_in[7];
    const float* b1    = (const float*)d_in[8];
    const float* wl2   = (const float*)d_in[9];
    const float* wr2   = (const float*)d_in[10];
    const float* att2  = (const float*)d_in[11];
    const float* b2    = (const float*)d_in[12];
    const float* wl3   = (const float*)d_in[13];
    const float* wr3   = (const float*)d_in[14];
    const float* att3  = (const float*)d_in[15];
    const float* b3    = (const float*)d_in[16];
    const float* wl4   = (const float*)d_in[17];
    const float* wr4   = (const float*)d_in[18];
    const float* att4  = (const float*)d_in[19];
    const float* b4    = (const float*)d_in[20];
    const float* n1w   = (const float*)d_in[21];
    const float* n1b   = (const float*)d_in[22];
    const float* n2w   = (const float*)d_in[23];
    const float* n2b   = (const float*)d_in[24];
    const float* n3w   = (const float*)d_in[25];
    const float* n3b   = (const float*)d_in[26];
    const float* n4w   = (const float*)d_in[27];
    const float* n4b   = (const float*)d_in[28];
    const float* lin_w = (const float*)d_in[29];
    const float* lin_b = (const float*)d_in[30];

    float *h0, *hA, *hB, *xl, *xr, *h4;
    cudaGetSymbolAddress((void**)&h0, g_h0);
    cudaGetSymbolAddress((void**)&hA, g_hA);
    cudaGetSymbolAddress((void**)&hB, g_hB);
    cudaGetSymbolAddress((void**)&xl, g_xl);
    cudaGetSymbolAddress((void**)&xr, g_xr);
    cudaGetSymbolAddress((void**)&h4, g_h4);

    // CSR by dst
    k_init_counts<<<(NN + 255) / 256, 256>>>();
    k_hist<<<(NE + 255) / 256, 256>>>(ei);
    k_scan<<<1, 1024>>>();
    k_cursor<<<(NN + 255) / 256, 256>>>();
    k_scatter<<<(NET + 255) / 256, 256>>>(ei);

    const dim3 gBig((NN + 127) / 128, 2);   // 157 x 2  (BN=128, BM=128, m=256)
    const dim3 gSm((NN + 127) / 128, 1);    // 157 x 1  (BN=128, BM=32)
    const int gatGrid = (NN + 7) / 8;       // 2500 blocks x 8 warps

    // text projection: h0 = x @ tp_w^T + tp_b  (K=768, M=32)
    gemm_tn<128, 32, 8, 2><<<gSm, 256>>>(x, tp_w, tp_b, h0, NN, 32, 768);

    // layer 1 (K=32, M=256)
    gemm_tn<128, 128, 8, 8><<<gBig, 256>>>(h0, wl1, nullptr, xl, NN, 256, 32);
    gemm_tn<128, 128, 8, 8><<<gBig, 256>>>(h0, wr1, nullptr, xr, NN, 256, 32);
    gat_kernel<8, 32, true><<<gatGrid, 256>>>(att1, b1, nullptr, n1w, n1b, hA);

    // layer 2 (K=256, M=256), residual hA
    gemm_tn<128, 128, 8, 8><<<gBig, 256>>>(hA, wl2, nullptr, xl, NN, 256, 256);
    gemm_tn<128, 128, 8, 8><<<gBig, 256>>>(hA, wr2, nullptr, xr, NN, 256, 256);
    gat_kernel<8, 32, true><<<gatGrid, 256>>>(att2, b2, hA, n2w, n2b, hB);

    // layer 3, residual hB
    gemm_tn<128, 128, 8, 8><<<gBig, 256>>>(hB, wl3, nullptr, xl, NN, 256, 256);
    gemm_tn<128, 128, 8, 8><<<gBig, 256>>>(hB, wr3, nullptr, xr, NN, 256, 256);
    gat_kernel<8, 32, true><<<gatGrid, 256>>>(att3, b3, hB, n3w, n3b, hA);

    // layer 4 (K=256, M=32, 1 head), no residual, no ELU
    gemm_tn<128, 32, 8, 2><<<gSm, 256>>>(hA, wl4, nullptr, xl, NN, 32, 256);
    gemm_tn<128, 32, 8, 2><<<gSm, 256>>>(hA, wr4, nullptr, xr, NN, 32, 256);
    gat_kernel<1, 32, false><<<gatGrid, 256>>>(att4, b4, nullptr, n4w, n4b, h4);

    // readout
    k_final<<<1, 256>>>(ptr, lin_w, lin_b, (float*)d_out);
}